// round 3
// baseline (speedup 1.0000x reference)
#include <cuda_runtime.h>
#include <math.h>

// Problem constants (match reference)
#define H_DIM   256
#define L_SEQ   512
#define N_BATCH 512
#define MAXC    64

// Precomputed positional embedding: 512 rows x 256 dims = 512 KB.
// __device__ global (no allocation) per harness rules.
__device__ float g_pe[L_SEQ * H_DIM];

// ---------------------------------------------------------------------------
// Kernel 1: compute pos_embed(row, h) once per launch. 512 blocks x 128 thr.
// pe[row, 2i]   = sin(row * 10000^(-i/128))
// pe[row, 2i+1] = cos(row * 10000^(-i/128))
// Double precision: angles reach ~511 rad and --use_fast_math sinf argument
// reduction is unusable there. ~1-2 us total, negligible vs 256 MB write.
// ---------------------------------------------------------------------------
__global__ void pe_kernel() {
    int row = blockIdx.x;          // 0..511
    int i   = threadIdx.x;         // 0..127  (pair index)
    // omega_inv = 10000^(2i/256) = 10000^(i/128); ang = row / omega_inv
    double factor = exp(-((double)i) * (9.210340371976184 / 128.0)); // ln(10000)
    double ang = (double)row * factor;
    double s, c;
    sincos(ang, &s, &c);
    g_pe[row * H_DIM + 2 * i]     = (float)s;
    g_pe[row * H_DIM + 2 * i + 1] = (float)c;
}

// ---------------------------------------------------------------------------
// Kernel 2: main embedding.
// Grid: L_SEQ * (N_BATCH/4) = 65536 blocks, 256 threads.
// Block bid -> row = bid >> 7, n_base = (bid & 127) * 4.
// Thread t  -> n = n_base + (t >> 6), h4 = t & 63 (float4 column).
// Row parity is block-uniform -> no divergence. Each warp writes 512 B
// contiguous. pe row (1 KB) and cat_table (256 KB) stay L1/L2 resident.
// ---------------------------------------------------------------------------
__global__ __launch_bounds__(256, 8)
void embed_kernel(const float* __restrict__ u_in,        // (N, L, 3)
                  const float* __restrict__ w_num,       // (T*H, 1) -> (32, 256)
                  const float* __restrict__ cat_table,   // (256, 256)
                  const int*   __restrict__ num_param_types, // (256,)
                  const int*   __restrict__ easy_index,  // (2048,)
                  float*       __restrict__ out)         // (N, L, H)
{
    const int bid = blockIdx.x;
    const int row    = bid >> 7;          // 0..511
    const int n_base = (bid & 127) << 2;  // 0,4,...,508
    const int t  = threadIdx.x;
    const int n  = n_base + (t >> 6);
    const int h4 = t & 63;                // float4 index within H

    // pos-embed chunk for this (row, h)
    const float4 pe = *reinterpret_cast<const float4*>(&g_pe[row * H_DIM + (h4 << 2)]);

    const long urow = ((long)n * L_SEQ + row) * 3;  // base of u_in[n, row, :]
    float4 r;

    if (row & 1) {
        // categorical row
        float tpar = u_in[urow + 2];
        float cval = u_in[urow + 0];
        int big = __float2int_rn(tpar * (float)MAXC + cval);
        int ei  = easy_index[big];
        const float4 e = *reinterpret_cast<const float4*>(&cat_table[(long)ei * H_DIM + (h4 << 2)]);
        r.x = e.x + pe.x; r.y = e.y + pe.y; r.z = e.z + pe.z; r.w = e.w + pe.w;
    } else {
        // numerical row
        float val = 2.0f * (u_in[urow + 1] - 0.5f);
        int pt = num_param_types[row >> 1];
        const float4 w = *reinterpret_cast<const float4*>(&w_num[(long)pt * H_DIM + (h4 << 2)]);
        r.x = fmaf(val, w.x, pe.x);
        r.y = fmaf(val, w.y, pe.y);
        r.z = fmaf(val, w.z, pe.z);
        r.w = fmaf(val, w.w, pe.w);
    }

    reinterpret_cast<float4*>(out)[((long)n * L_SEQ + row) * (H_DIM / 4) + h4] = r;
}

// ---------------------------------------------------------------------------
// Launch. Inputs (metadata order):
//   0: u_in (N,L,3) f32   1: w_num (8192,1) f32   2: cat_table (256,256) f32
//   3: cat_rows i32       4: num_rows i32         5: num_param_types i32
//   6: easy_index i32
// ---------------------------------------------------------------------------
extern "C" void kernel_launch(void* const* d_in, const int* in_sizes, int n_in,
                              void* d_out, int out_size) {
    const float* u_in      = (const float*)d_in[0];
    const float* w_num     = (const float*)d_in[1];
    const float* cat_table = (const float*)d_in[2];
    const int*   npt       = (const int*)d_in[5];
    const int*   easy      = (const int*)d_in[6];
    float* out = (float*)d_out;

    pe_kernel<<<L_SEQ, H_DIM / 2>>>();
    embed_kernel<<<L_SEQ * (N_BATCH / 4), 256>>>(u_in, w_num, cat_table, npt, easy, out);
}

// round 9
// speedup vs baseline: 1.4028x; 1.4028x over previous
#include <cuda_runtime.h>
#include <math.h>

// Problem constants (match reference)
#define H_DIM   256
#define L_SEQ   512
#define N_BATCH 512
#define MAXC    64

// Precomputed positional embedding: 512 rows x 256 dims = 512 KB.
__device__ float g_pe[L_SEQ * H_DIM];

// ---------------------------------------------------------------------------
// Kernel 1: positional embedding, computed per launch (must be deterministic,
// no caching allowed). Double precision: angles reach ~511 rad; fast-math
// sinf argument reduction is unusable there. ~1-2 us.
// ---------------------------------------------------------------------------
__global__ void pe_kernel() {
    int row = blockIdx.x;          // 0..511
    int i   = threadIdx.x;         // 0..127  (pair index)
    double factor = exp(-((double)i) * (9.210340371976184 / 128.0)); // ln(10000)
    double ang = (double)row * factor;
    double s, c;
    sincos(ang, &s, &c);
    g_pe[row * H_DIM + 2 * i]     = (float)s;
    g_pe[row * H_DIM + 2 * i + 1] = (float)c;
}

// ---------------------------------------------------------------------------
// Kernel 2: main embedding, unroll-4 over n for memory-level parallelism.
// Grid: 512 rows x 32 n-chunks = 16384 blocks, 256 threads.
//   row    = bid >> 5
//   n_base = (bid & 31) * 16
//   thread t: h4 = t & 63 (float4 col), g = t >> 6 (0..3)
//   handles n = n_base + g + {0,4,8,12}  -> 4 independent load chains.
// Row parity is block-uniform (no divergence). Within a warp n is uniform
// (scalar loads broadcast). Each warp's store = 512 B contiguous, x4.
// ---------------------------------------------------------------------------
__global__ __launch_bounds__(256, 4)
void embed_kernel(const float* __restrict__ u_in,            // (N, L, 3)
                  const float* __restrict__ w_num,           // (32, 256)
                  const float* __restrict__ cat_table,       // (n_emb, 256)
                  const int*   __restrict__ num_param_types, // (256,)
                  const int*   __restrict__ easy_index,      // (2048,)
                  float*       __restrict__ out)             // (N, L, H)
{
    const int bid    = blockIdx.x;
    const int row    = bid >> 5;           // 0..511
    const int n_base = (bid & 31) << 4;    // 0,16,...,496
    const int t      = threadIdx.x;
    const int g      = t >> 6;             // 0..3
    const int h4     = t & 63;             // float4 index within H

    const float4 pe = *reinterpret_cast<const float4*>(&g_pe[row * H_DIM + (h4 << 2)]);

    int  n[4];
    long urow[4];
#pragma unroll
    for (int j = 0; j < 4; j++) {
        n[j]    = n_base + g + (j << 2);
        urow[j] = ((long)n[j] * L_SEQ + row) * 3;
    }

    float4 r[4];

    if (row & 1) {
        // categorical rows: u -> easy_index -> cat_table gather, 4-wide MLP
        float tpar[4], cval[4];
#pragma unroll
        for (int j = 0; j < 4; j++) {
            tpar[j] = u_in[urow[j] + 2];
            cval[j] = u_in[urow[j] + 0];
        }
        int ei[4];
#pragma unroll
        for (int j = 0; j < 4; j++) {
            int big = __float2int_rn(tpar[j] * (float)MAXC + cval[j]);
            ei[j] = easy_index[big];
        }
#pragma unroll
        for (int j = 0; j < 4; j++) {
            const float4 e = *reinterpret_cast<const float4*>(
                &cat_table[(long)ei[j] * H_DIM + (h4 << 2)]);
            r[j].x = e.x + pe.x; r[j].y = e.y + pe.y;
            r[j].z = e.z + pe.z; r[j].w = e.w + pe.w;
        }
    } else {
        // numerical rows: w row depends only on `row` -> single w load
        float val[4];
#pragma unroll
        for (int j = 0; j < 4; j++)
            val[j] = 2.0f * (u_in[urow[j] + 1] - 0.5f);
        const int pt = num_param_types[row >> 1];
        const float4 w = *reinterpret_cast<const float4*>(
            &w_num[(long)pt * H_DIM + (h4 << 2)]);
#pragma unroll
        for (int j = 0; j < 4; j++) {
            r[j].x = fmaf(val[j], w.x, pe.x);
            r[j].y = fmaf(val[j], w.y, pe.y);
            r[j].z = fmaf(val[j], w.z, pe.z);
            r[j].w = fmaf(val[j], w.w, pe.w);
        }
    }

#pragma unroll
    for (int j = 0; j < 4; j++) {
        reinterpret_cast<float4*>(out)[((long)n[j] * L_SEQ + row) * (H_DIM / 4) + h4] = r[j];
    }
}

// ---------------------------------------------------------------------------
// Launch. Inputs (metadata order):
//   0: u_in (N,L,3) f32   1: w_num (8192,1) f32   2: cat_table f32
//   3: cat_rows i32       4: num_rows i32         5: num_param_types i32
//   6: easy_index i32
// ---------------------------------------------------------------------------
extern "C" void kernel_launch(void* const* d_in, const int* in_sizes, int n_in,
                              void* d_out, int out_size) {
    const float* u_in      = (const float*)d_in[0];
    const float* w_num     = (const float*)d_in[1];
    const float* cat_table = (const float*)d_in[2];
    const int*   npt       = (const int*)d_in[5];
    const int*   easy      = (const int*)d_in[6];
    float* out = (float*)d_out;

    pe_kernel<<<L_SEQ, H_DIM / 2>>>();
    embed_kernel<<<L_SEQ * (N_BATCH / 16), 256>>>(u_in, w_num, cat_table, npt, easy, out);
}

// round 11
// speedup vs baseline: 1.5397x; 1.0975x over previous
#include <cuda_runtime.h>
#include <math.h>

// Problem constants (match reference)
#define H_DIM   256
#define L_SEQ   512
#define N_BATCH 512
#define MAXC    64

// Precomputed positional embedding: 512 rows x 256 dims = 512 KB.
__device__ float g_pe[L_SEQ * H_DIM];

// ---------------------------------------------------------------------------
// Kernel 1: positional embedding, computed per launch (must be deterministic,
// no caching allowed). Double precision: angles reach ~511 rad; fast-math
// sinf argument reduction is unusable there. ~2 us.
// ---------------------------------------------------------------------------
__global__ void pe_kernel() {
    int row = blockIdx.x;          // 0..511
    int i   = threadIdx.x;         // 0..127  (pair index)
    double factor = exp(-((double)i) * (9.210340371976184 / 128.0)); // ln(10000)
    double ang = (double)row * factor;
    double s, c;
    sincos(ang, &s, &c);
    g_pe[row * H_DIM + 2 * i]     = (float)s;
    g_pe[row * H_DIM + 2 * i + 1] = (float)c;
}

// ---------------------------------------------------------------------------
// Kernel 2: main embedding, unroll-8 over n for memory-level parallelism.
// Grid: 512 rows x 16 n-chunks = 8192 blocks, 256 threads.
//   row    = bid >> 4
//   n_base = (bid & 15) * 32
//   thread t: h4 = t & 63 (float4 col), g = t >> 6 (0..3)
//   handles n = n_base + g + {0,4,...,28} -> 8 independent load chains.
// j-strides are compile-time constants (u_in: 24 KB, out: 2 MB) so addresses
// collapse to base+immediate in SASS; regs stay under the occ-4 budget.
// Stores use __stcs (evict-first): output is never re-read.
// ---------------------------------------------------------------------------
__global__ __launch_bounds__(256, 4)
void embed_kernel(const float* __restrict__ u_in,            // (N, L, 3)
                  const float* __restrict__ w_num,           // (32, 256)
                  const float* __restrict__ cat_table,       // (n_emb, 256)
                  const int*   __restrict__ num_param_types, // (256,)
                  const int*   __restrict__ easy_index,      // (2048,)
                  float*       __restrict__ out)             // (N, L, H)
{
    const int bid    = blockIdx.x;
    const int row    = bid >> 4;           // 0..511
    const int n_base = (bid & 15) << 5;    // 0,32,...,480
    const int t      = threadIdx.x;
    const int g      = t >> 6;             // 0..3
    const int h4     = t & 63;             // float4 index within H

    const float4 pe = *reinterpret_cast<const float4*>(&g_pe[row * H_DIM + (h4 << 2)]);

    const int  n0    = n_base + g;                       // j-th n = n0 + 4*j
    const long urow0 = ((long)n0 * L_SEQ + row) * 3;     // +j*4*512*3
    float4* const out4 = reinterpret_cast<float4*>(out);
    const long obase = ((long)n0 * L_SEQ + row) * (H_DIM / 4) + h4;  // +j*4*512*64

    float4 r[8];

    if (row & 1) {
        // categorical rows: u -> easy_index -> cat_table gather, 8-wide MLP
        float tpar[8], cval[8];
#pragma unroll
        for (int j = 0; j < 8; j++) {
            const long u = urow0 + (long)j * (4L * L_SEQ * 3);
            tpar[j] = u_in[u + 2];
            cval[j] = u_in[u + 0];
        }
        int ei[8];
#pragma unroll
        for (int j = 0; j < 8; j++) {
            int big = __float2int_rn(tpar[j] * (float)MAXC + cval[j]);
            ei[j] = easy_index[big];
        }
#pragma unroll
        for (int j = 0; j < 8; j++) {
            const float4 e = *reinterpret_cast<const float4*>(
                &cat_table[(long)ei[j] * H_DIM + (h4 << 2)]);
            r[j].x = e.x + pe.x; r[j].y = e.y + pe.y;
            r[j].z = e.z + pe.z; r[j].w = e.w + pe.w;
        }
    } else {
        // numerical rows: w row depends only on `row` -> single w load
        float val[8];
#pragma unroll
        for (int j = 0; j < 8; j++) {
            const long u = urow0 + (long)j * (4L * L_SEQ * 3);
            val[j] = 2.0f * (u_in[u + 1] - 0.5f);
        }
        const int pt = num_param_types[row >> 1];
        const float4 w = *reinterpret_cast<const float4*>(
            &w_num[(long)pt * H_DIM + (h4 << 2)]);
#pragma unroll
        for (int j = 0; j < 8; j++) {
            r[j].x = fmaf(val[j], w.x, pe.x);
            r[j].y = fmaf(val[j], w.y, pe.y);
            r[j].z = fmaf(val[j], w.z, pe.z);
            r[j].w = fmaf(val[j], w.w, pe.w);
        }
    }

#pragma unroll
    for (int j = 0; j < 8; j++) {
        __stcs(&out4[obase + (long)j * (4L * L_SEQ * (H_DIM / 4))], r[j]);
    }
}

// ---------------------------------------------------------------------------
// Launch. Inputs (metadata order):
//   0: u_in (N,L,3) f32   1: w_num (8192,1) f32   2: cat_table f32
//   3: cat_rows i32       4: num_rows i32         5: num_param_types i32
//   6: easy_index i32
// ---------------------------------------------------------------------------
extern "C" void kernel_launch(void* const* d_in, const int* in_sizes, int n_in,
                              void* d_out, int out_size) {
    const float* u_in      = (const float*)d_in[0];
    const float* w_num     = (const float*)d_in[1];
    const float* cat_table = (const float*)d_in[2];
    const int*   npt       = (const int*)d_in[5];
    const int*   easy      = (const int*)d_in[6];
    float* out = (float*)d_out;

    pe_kernel<<<L_SEQ, H_DIM / 2>>>();
    embed_kernel<<<L_SEQ * (N_BATCH / 32), 256>>>(u_in, w_num, cat_table, npt, easy, out);
}